// round 6
// baseline (speedup 1.0000x reference)
#include <cuda_runtime.h>
#include <cuda_bf16.h>

// Problem dims (fixed by the dataset)
#define B  512
#define T  1024
#define IN 128
#define H  256

// ---------------- scratch (device globals: no allocation allowed) -------------
__device__ float    g_cur1[(size_t)B * T * H];   // [B][T][H]  512 MB
__device__ float    g_w2t[H * H];                // [j][h]  (W2 transposed)
__device__ unsigned g_spk[(size_t)B * T * 8];    // spk2 ballots, 16 MB

// packed fp32x2 helpers (sm_103a — only reachable via PTX)
#define FMA2(acc, a, b) \
    asm("fma.rn.f32x2 %0, %1, %2, %0;" : "+l"(acc) : "l"(a), "l"(b))
#define ADD2(d, a, b) \
    asm("add.rn.f32x2 %0, %1, %2;" : "=l"(d) : "l"(a), "l"(b))
#define PACK2(d, f) \
    asm("mov.b64 %0, {%1, %1};" : "=l"(d) : "r"(__float_as_uint(f)))

// ---------------- phase 1: cur1 = x @ W1^T + b1 -------------------------------
// 64x128 tile, two K-stages of 64, 4x8 micro-tile, FFMA2.
// W1 is transposed inline during the smem fill (no prep kernel).
// Blocks with blockIdx.x==0 additionally write the W2 transpose for the scan.
#define BM  64
#define BN  128
#define BKK 64
#define BNP (BN + 4)     // padded ws row: 132 floats (16B aligned, no STS conflicts)
#define GSMEM ((BM * BKK + BKK * BNP) * 4)   // 50176 B -> opt-in dynamic smem

__global__ void __launch_bounds__(256) gemm_cur1(const float* __restrict__ x,
                                                 const float* __restrict__ W1,
                                                 const float* __restrict__ b1,
                                                 const float* __restrict__ W2) {
    extern __shared__ float smem_g[];
    float (*xs)[BKK] = (float(*)[BKK])smem_g;                    // 64x64
    float (*ws)[BNP] = (float(*)[BNP])(smem_g + BM * BKK);       // 64x132

    const int tid = threadIdx.x;

    // side work: W2 transpose (2 blocks, hidden in wave 1 of ~28)
    if (blockIdx.x == 0) {
        int base = blockIdx.y * 256 + tid;          // 0..511
        #pragma unroll 4
        for (int i = 0; i < 128; i++) {
            int idx = base + i * 512;               // coalesced read of W2 [H][H]
            g_w2t[(idx & 255) * H + (idx >> 8)] = W2[idx];
        }
    }

    const int bm = blockIdx.x * BM;
    const int bn = blockIdx.y * BN;
    const int tx = tid & 15;         // 8 output cols = 4 f32x2
    const int ty = tid >> 4;         // 4 output rows

    unsigned long long acc[4][4];
    #pragma unroll
    for (int r = 0; r < 4; r++)
        #pragma unroll
        for (int p = 0; p < 4; p++) acc[r][p] = 0ull;

    for (int k0 = 0; k0 < IN; k0 += BKK) {
        // xs: direct copy, coalesced
        #pragma unroll
        for (int l = 0; l < 4; l++) {
            int idx = tid + l * 256;
            int r = idx >> 4, c4 = idx & 15;
            *(float4*)&xs[r][c4 * 4] =
                *(const float4*)&x[(size_t)(bm + r) * IN + k0 + c4 * 4];
        }
        // ws[k][h] = W1[bn+h][k0+k]: inline transpose
        #pragma unroll
        for (int l = 0; l < 8; l++) {
            int k  = tid & 63;
            int hq = (tid >> 6) + l * 4;            // 0..31
            const float* w1p = &W1[(size_t)(bn + hq * 4) * IN + k0 + k];
            float4 v;
            v.x = w1p[0 * IN];
            v.y = w1p[1 * IN];
            v.z = w1p[2 * IN];
            v.w = w1p[3 * IN];
            *(float4*)&ws[k][hq * 4] = v;
        }
        __syncthreads();

        #pragma unroll 8
        for (int k = 0; k < BKK; k++) {
            ulonglong2 bq0 = *(ulonglong2*)&ws[k][tx * 8];
            ulonglong2 bq1 = *(ulonglong2*)&ws[k][tx * 8 + 4];
            #pragma unroll
            for (int r = 0; r < 4; r++) {
                unsigned long long ad;
                PACK2(ad, xs[ty * 4 + r][k]);
                FMA2(acc[r][0], ad, bq0.x);
                FMA2(acc[r][1], ad, bq0.y);
                FMA2(acc[r][2], ad, bq1.x);
                FMA2(acc[r][3], ad, bq1.y);
            }
        }
        __syncthreads();
    }

    ulonglong2 bias0 = *(const ulonglong2*)&b1[bn + tx * 8];
    ulonglong2 bias1 = *(const ulonglong2*)&b1[bn + tx * 8 + 4];
    #pragma unroll
    for (int r = 0; r < 4; r++) {
        ulonglong2 o0, o1;
        ADD2(o0.x, acc[r][0], bias0.x);
        ADD2(o0.y, acc[r][1], bias0.y);
        ADD2(o1.x, acc[r][2], bias1.x);
        ADD2(o1.y, acc[r][3], bias1.y);
        float* dst = &g_cur1[(size_t)(bm + ty * 4 + r) * H + bn + tx * 8];
        *(ulonglong2*)dst       = o0;
        *(ulonglong2*)(dst + 4) = o1;
    }
}

// ---------------- phase 2: sequential scan, one CTA per batch element ---------
// 256 threads; thread t owns neuron h=t.
// Per step: ONE full barrier + one 2-warp named barrier.
//   Slice g (warps 2g,2g+1) consumes exactly the ballot words its own warps
//   produce -> pair barrier suffices for bits. part[] is double-buffered so
//   the single full barrier fences write(t+2) from read(t).
// Gather: 64-bit mask, 4 rows in flight, packed f32x2 adds.
__global__ void __launch_bounds__(256) scan_kernel(const float* __restrict__ b2,
                                                   const float* __restrict__ wout,
                                                   const float* __restrict__ boutp,
                                                   const float* __restrict__ pb1,
                                                   const float* __restrict__ pb2,
                                                   const float* __restrict__ pbo,
                                                   float* __restrict__ out) {
    const int b    = blockIdx.x;
    const int tid  = threadIdx.x;
    const int lane = tid & 31;
    const int wid  = tid >> 5;
    const int g    = tid >> 6;   // row-slice 0..3
    const int c    = tid & 63;   // float4 chunk 0..63

    const float bt1 = fminf(fmaxf(pb1[0], 0.f), 1.f);
    const float bt2 = fminf(fmaxf(pb2[0], 0.f), 1.f);
    const float bto = fminf(fmaxf(pbo[0], 0.f), 1.f);
    const float boutv = boutp[0];
    const float b2v   = b2[tid];

    __shared__ unsigned bits[8];
    __shared__ float    part[2][4][H];   // double-buffered partials (8KB)
    __shared__ float    wout_sm[H];      // 1KB

    wout_sm[tid] = wout[tid];

    float mem1 = 0.f, mem2 = 0.f;
    float s1p = 0.f, s2p = 0.f;

    const float* c1p   = g_cur1 + (size_t)b * T * H + tid;
    unsigned*    spkp  = g_spk + (size_t)b * T * 8;
    float*       outp  = out + (size_t)b * T;
    const float* rbase = g_w2t + (size_t)(64 * g) * H + c * 4;  // slice row base

    // software-pipeline cur1 one step ahead
    float c1 = c1p[0];
    __syncthreads();   // wout_sm + initial state visible

    for (int t = 0; t < T; t++) {
        float c1n = (t + 1 < T) ? c1p[(size_t)(t + 1) * H] : 0.f;

        // layer 1 membrane update (reset uses previous-step spike)
        mem1 = bt1 * mem1 + c1 - s1p;
        bool s1 = mem1 > 1.0f;
        unsigned bal = __ballot_sync(0xffffffffu, s1);
        if (lane == 0) bits[wid] = bal;
        s1p = s1 ? 1.f : 0.f;

        // pair barrier: slice g's two warps exchange their two ballot words
        asm volatile("bar.sync %0, 64;" :: "r"(g + 1) : "memory");

        unsigned long long m =
            ((unsigned long long)bits[2 * g + 1] << 32) | (unsigned long long)bits[2 * g];

        // gather: 4 rows in flight, packed f32x2 accumulate
        ulonglong2 A, Bq, C, D;
        A.x = A.y = Bq.x = Bq.y = C.x = C.y = D.x = D.y = 0ull;
        int n = __popcll(m);
        for (int k = 0; k + 4 <= n; k += 4) {
            int j0 = __ffsll(m) - 1; m &= m - 1;
            int j1 = __ffsll(m) - 1; m &= m - 1;
            int j2 = __ffsll(m) - 1; m &= m - 1;
            int j3 = __ffsll(m) - 1; m &= m - 1;
            ulonglong2 w0 = *(const ulonglong2*)(rbase + (size_t)j0 * H);
            ulonglong2 w1 = *(const ulonglong2*)(rbase + (size_t)j1 * H);
            ulonglong2 w2 = *(const ulonglong2*)(rbase + (size_t)j2 * H);
            ulonglong2 w3 = *(const ulonglong2*)(rbase + (size_t)j3 * H);
            ADD2(A.x,  A.x,  w0.x); ADD2(A.y,  A.y,  w0.y);
            ADD2(Bq.x, Bq.x, w1.x); ADD2(Bq.y, Bq.y, w1.y);
            ADD2(C.x,  C.x,  w2.x); ADD2(C.y,  C.y,  w2.y);
            ADD2(D.x,  D.x,  w3.x); ADD2(D.y,  D.y,  w3.y);
        }
        while (m) {
            int j = __ffsll(m) - 1; m &= m - 1;
            ulonglong2 w0 = *(const ulonglong2*)(rbase + (size_t)j * H);
            ADD2(A.x, A.x, w0.x); ADD2(A.y, A.y, w0.y);
        }
        ADD2(A.x, A.x, Bq.x); ADD2(A.y, A.y, Bq.y);
        ADD2(C.x, C.x, D.x);  ADD2(C.y, C.y, D.y);
        ADD2(A.x, A.x, C.x);  ADD2(A.y, A.y, C.y);
        *(ulonglong2*)&part[t & 1][g][c * 4] = A;

        __syncthreads();                          // the ONE full barrier

        float cur2 = b2v + ((part[t & 1][0][tid] + part[t & 1][1][tid]) +
                            (part[t & 1][2][tid] + part[t & 1][3][tid]));

        // layer 2 membrane update
        mem2 = bt2 * mem2 + cur2 - s2p;
        bool s2 = mem2 > 1.0f;
        s2p = s2 ? 1.f : 0.f;

        // record spk2 ballot (off critical path; reduced after the loop)
        unsigned bal2 = __ballot_sync(0xffffffffu, s2);
        if (lane == 0) spkp[(size_t)t * 8 + wid] = bal2;

        c1 = c1n;
    }

    // ---------------- deferred output: out_t = bout + sum(spk2 .* wout) -------
    __syncthreads();
    float* out_s = &part[0][0][0];                // reuse 4KB as out_s[1024]
    #pragma unroll
    for (int i = 0; i < 4; i++) {
        int t = tid + i * 256;
        float o = boutv;
        #pragma unroll
        for (int w = 0; w < 8; w++) {
            unsigned m = spkp[(size_t)t * 8 + w];
            const float* wo = wout_sm + w * 32;
            while (m) {
                int j = __ffs(m) - 1; m &= m - 1;
                o += wo[j];
            }
        }
        out_s[t] = o;
    }
    __syncthreads();
    if (tid == 0) {                               // exact serial memo recurrence
        float memo = 0.f;
        for (int t = 0; t < T; t++) {
            memo = bto * memo + out_s[t];
            out_s[t] = memo;
        }
    }
    __syncthreads();
    #pragma unroll
    for (int i = 0; i < 4; i++) {
        int t = tid + i * 256;
        outp[t] = out_s[t];
    }
}

// ---------------- launcher ----------------------------------------------------
extern "C" void kernel_launch(void* const* d_in, const int* in_sizes, int n_in,
                              void* d_out, int out_size) {
    const float* x     = (const float*)d_in[0];   // [B,T,IN]
    const float* W1    = (const float*)d_in[1];   // [H,IN]
    const float* b1    = (const float*)d_in[2];   // [H]
    const float* W2    = (const float*)d_in[3];   // [H,H]
    const float* b2    = (const float*)d_in[4];   // [H]
    const float* Wout  = (const float*)d_in[5];   // [1,H]
    const float* bout  = (const float*)d_in[6];   // [1]
    const float* beta1 = (const float*)d_in[7];
    const float* beta2 = (const float*)d_in[8];
    const float* betao = (const float*)d_in[9];
    float* out = (float*)d_out;                   // [B,T,1]

    cudaFuncSetAttribute(gemm_cur1,
                         cudaFuncAttributeMaxDynamicSharedMemorySize, GSMEM);

    dim3 ggrid(B * T / BM, H / BN);
    gemm_cur1<<<ggrid, 256, GSMEM>>>(x, W1, b1, W2);

    scan_kernel<<<B, 256>>>(b2, Wout, bout, beta1, beta2, betao, out);
}

// round 7
// speedup vs baseline: 1.0341x; 1.0341x over previous
#include <cuda_runtime.h>
#include <cuda_bf16.h>

// Problem dims (fixed by the dataset)
#define B  512
#define T  1024
#define IN 128
#define H  256

// ---------------- scratch (device globals: no allocation allowed) -------------
__device__ float    g_cur1[(size_t)B * T * H];   // [B][T][H]  512 MB
__device__ float    g_w2t[H * H];                // [j][h]  (W2 transposed)
__device__ unsigned g_spk[(size_t)B * T * 8];    // spk2 ballots, 16 MB

// packed fp32x2 helpers (sm_103a — only reachable via PTX)
#define FMA2(acc, a, b) \
    asm("fma.rn.f32x2 %0, %1, %2, %0;" : "+l"(acc) : "l"(a), "l"(b))
#define ADD2(d, a, b) \
    asm("add.rn.f32x2 %0, %1, %2;" : "=l"(d) : "l"(a), "l"(b))
#define PACK2(d, f) \
    asm("mov.b64 %0, {%1, %1};" : "=l"(d) : "r"(__float_as_uint(f)))

// ---------------- phase 1: cur1 = x @ W1^T + b1 -------------------------------
// 64x128 tile, two K-stages of 64, 4x8 micro-tile, FFMA2.
// W1 transposed inline during smem fill; blockIdx.x==0 also transposes W2.
#define BM  64
#define BN  128
#define BKK 64
#define BNP (BN + 4)
#define GSMEM ((BM * BKK + BKK * BNP) * 4)   // 50176 B -> opt-in dynamic smem

__global__ void __launch_bounds__(256) gemm_cur1(const float* __restrict__ x,
                                                 const float* __restrict__ W1,
                                                 const float* __restrict__ b1,
                                                 const float* __restrict__ W2) {
    extern __shared__ float smem_g[];
    float (*xs)[BKK] = (float(*)[BKK])smem_g;                    // 64x64
    float (*ws)[BNP] = (float(*)[BNP])(smem_g + BM * BKK);       // 64x132

    const int tid = threadIdx.x;

    if (blockIdx.x == 0) {                      // W2 transpose side-work
        int base = blockIdx.y * 256 + tid;
        #pragma unroll 4
        for (int i = 0; i < 128; i++) {
            int idx = base + i * 512;
            g_w2t[(idx & 255) * H + (idx >> 8)] = W2[idx];
        }
    }

    const int bm = blockIdx.x * BM;
    const int bn = blockIdx.y * BN;
    const int tx = tid & 15;
    const int ty = tid >> 4;

    unsigned long long acc[4][4];
    #pragma unroll
    for (int r = 0; r < 4; r++)
        #pragma unroll
        for (int p = 0; p < 4; p++) acc[r][p] = 0ull;

    for (int k0 = 0; k0 < IN; k0 += BKK) {
        #pragma unroll
        for (int l = 0; l < 4; l++) {
            int idx = tid + l * 256;
            int r = idx >> 4, c4 = idx & 15;
            *(float4*)&xs[r][c4 * 4] =
                *(const float4*)&x[(size_t)(bm + r) * IN + k0 + c4 * 4];
        }
        #pragma unroll
        for (int l = 0; l < 8; l++) {
            int k  = tid & 63;
            int hq = (tid >> 6) + l * 4;
            const float* w1p = &W1[(size_t)(bn + hq * 4) * IN + k0 + k];
            float4 v;
            v.x = w1p[0 * IN];
            v.y = w1p[1 * IN];
            v.z = w1p[2 * IN];
            v.w = w1p[3 * IN];
            *(float4*)&ws[k][hq * 4] = v;
        }
        __syncthreads();

        #pragma unroll 8
        for (int k = 0; k < BKK; k++) {
            ulonglong2 bq0 = *(ulonglong2*)&ws[k][tx * 8];
            ulonglong2 bq1 = *(ulonglong2*)&ws[k][tx * 8 + 4];
            #pragma unroll
            for (int r = 0; r < 4; r++) {
                unsigned long long ad;
                PACK2(ad, xs[ty * 4 + r][k]);
                FMA2(acc[r][0], ad, bq0.x);
                FMA2(acc[r][1], ad, bq0.y);
                FMA2(acc[r][2], ad, bq1.x);
                FMA2(acc[r][3], ad, bq1.y);
            }
        }
        __syncthreads();
    }

    ulonglong2 bias0 = *(const ulonglong2*)&b1[bn + tx * 8];
    ulonglong2 bias1 = *(const ulonglong2*)&b1[bn + tx * 8 + 4];
    #pragma unroll
    for (int r = 0; r < 4; r++) {
        ulonglong2 o0, o1;
        ADD2(o0.x, acc[r][0], bias0.x);
        ADD2(o0.y, acc[r][1], bias0.y);
        ADD2(o1.x, acc[r][2], bias1.x);
        ADD2(o1.y, acc[r][3], bias1.y);
        float* dst = &g_cur1[(size_t)(bm + ty * 4 + r) * H + bn + tx * 8];
        *(ulonglong2*)dst       = o0;
        *(ulonglong2*)(dst + 4) = o1;
    }
}

// ---------------- phase 2: sequential scan, one CTA per batch element ---------
// 256 threads. Warp w owns: layer-1/2 neurons [32w, 32w+32) (thread tid = neuron
// tid), AND gather rows [32w, 32w+32) across ALL 256 columns (lane l owns the
// 8-float chunk [8l, 8l+8)). The gather mask is the warp's OWN ballot word:
// no smem, no barrier before the gather. 32-bit ffs/blsr; each row does two
// LDG.128 (+512B immediate) and 4 packed ADD2. ONE __syncthreads per step
// (partials double-buffered).
__global__ void __launch_bounds__(256) scan_kernel(const float* __restrict__ b2,
                                                   const float* __restrict__ wout,
                                                   const float* __restrict__ boutp,
                                                   const float* __restrict__ pb1,
                                                   const float* __restrict__ pb2,
                                                   const float* __restrict__ pbo,
                                                   float* __restrict__ out) {
    const int b    = blockIdx.x;
    const int tid  = threadIdx.x;
    const int lane = tid & 31;
    const int wid  = tid >> 5;

    const float bt1 = fminf(fmaxf(pb1[0], 0.f), 1.f);
    const float bt2 = fminf(fmaxf(pb2[0], 0.f), 1.f);
    const float bto = fminf(fmaxf(pbo[0], 0.f), 1.f);
    const float boutv = boutp[0];
    const float b2v   = b2[tid];

    __shared__ float part[2][8][H];      // double-buffered partials (16KB)
    __shared__ float wout_sm[H];         // 1KB

    wout_sm[tid] = wout[tid];

    float mem1 = 0.f, mem2 = 0.f;
    float s1p = 0.f, s2p = 0.f;

    const float* c1p  = g_cur1 + (size_t)b * T * H + tid;
    unsigned*    spkp = g_spk + (size_t)b * T * 8;
    float*       outp = out + (size_t)b * T;
    // warp wid's row block, lane's column chunk (8 floats; 2nd half at +4)
    const float* rbase = g_w2t + (size_t)(32 * wid) * H + lane * 8;

    float c1 = c1p[0];
    __syncthreads();

    for (int t = 0; t < T; t++) {
        float c1n = (t + 1 < T) ? c1p[(size_t)(t + 1) * H] : 0.f;

        // layer 1 membrane update (reset uses previous-step spike)
        mem1 = bt1 * mem1 + c1 - s1p;
        bool s1 = mem1 > 1.0f;
        unsigned m = __ballot_sync(0xffffffffu, s1);   // == gather mask (own rows)
        s1p = s1 ? 1.f : 0.f;

        // gather: 2 rows in flight, 2 chunks per row, packed adds
        ulonglong2 A0, A1, B0, B1;
        A0.x = A0.y = A1.x = A1.y = 0ull;
        B0.x = B0.y = B1.x = B1.y = 0ull;
        while (m) {
            int j0 = __ffs(m) - 1; m &= m - 1;
            const float* p0 = rbase + (size_t)j0 * H;
            if (m) {
                int j1 = __ffs(m) - 1; m &= m - 1;
                const float* p1 = rbase + (size_t)j1 * H;
                ulonglong2 w00 = *(const ulonglong2*)p0;
                ulonglong2 w01 = *(const ulonglong2*)(p0 + 4);
                ulonglong2 w10 = *(const ulonglong2*)p1;
                ulonglong2 w11 = *(const ulonglong2*)(p1 + 4);
                ADD2(A0.x, A0.x, w00.x); ADD2(A0.y, A0.y, w00.y);
                ADD2(A1.x, A1.x, w01.x); ADD2(A1.y, A1.y, w01.y);
                ADD2(B0.x, B0.x, w10.x); ADD2(B0.y, B0.y, w10.y);
                ADD2(B1.x, B1.x, w11.x); ADD2(B1.y, B1.y, w11.y);
            } else {
                ulonglong2 w00 = *(const ulonglong2*)p0;
                ulonglong2 w01 = *(const ulonglong2*)(p0 + 4);
                ADD2(A0.x, A0.x, w00.x); ADD2(A0.y, A0.y, w00.y);
                ADD2(A1.x, A1.x, w01.x); ADD2(A1.y, A1.y, w01.y);
            }
        }
        ADD2(A0.x, A0.x, B0.x); ADD2(A0.y, A0.y, B0.y);
        ADD2(A1.x, A1.x, B1.x); ADD2(A1.y, A1.y, B1.y);
        *(ulonglong2*)&part[t & 1][wid][lane * 8]     = A0;
        *(ulonglong2*)&part[t & 1][wid][lane * 8 + 4] = A1;

        __syncthreads();                          // the ONE barrier per step

        // reduce 8 warp-partials for this thread's column
        const float* pp = &part[t & 1][0][tid];
        float r0 = pp[0 * H] + pp[1 * H];
        float r1 = pp[2 * H] + pp[3 * H];
        float r2 = pp[4 * H] + pp[5 * H];
        float r3 = pp[6 * H] + pp[7 * H];
        float cur2 = b2v + ((r0 + r1) + (r2 + r3));

        // layer 2 membrane update
        mem2 = bt2 * mem2 + cur2 - s2p;
        bool s2 = mem2 > 1.0f;
        s2p = s2 ? 1.f : 0.f;

        unsigned bal2 = __ballot_sync(0xffffffffu, s2);
        if (lane == 0) spkp[(size_t)t * 8 + wid] = bal2;

        c1 = c1n;
    }

    // ---------------- deferred output: out_t = bout + sum(spk2 .* wout) -------
    __syncthreads();
    float* out_s = &part[0][0][0];                // reuse smem as out_s[1024]
    #pragma unroll
    for (int i = 0; i < 4; i++) {
        int t = tid + i * 256;
        float o = boutv;
        #pragma unroll
        for (int w = 0; w < 8; w++) {
            unsigned m = spkp[(size_t)t * 8 + w];
            const float* wo = wout_sm + w * 32;
            while (m) {
                int j = __ffs(m) - 1; m &= m - 1;
                o += wo[j];
            }
        }
        out_s[t] = o;
    }
    __syncthreads();
    if (tid == 0) {                               // exact serial memo recurrence
        float memo = 0.f;
        for (int t = 0; t < T; t++) {
            memo = bto * memo + out_s[t];
            out_s[t] = memo;
        }
    }
    __syncthreads();
    #pragma unroll
    for (int i = 0; i < 4; i++) {
        int t = tid + i * 256;
        outp[t] = out_s[t];
    }
}

// ---------------- launcher ----------------------------------------------------
extern "C" void kernel_launch(void* const* d_in, const int* in_sizes, int n_in,
                              void* d_out, int out_size) {
    const float* x     = (const float*)d_in[0];   // [B,T,IN]
    const float* W1    = (const float*)d_in[1];   // [H,IN]
    const float* b1    = (const float*)d_in[2];   // [H]
    const float* W2    = (const float*)d_in[3];   // [H,H]
    const float* b2    = (const float*)d_in[4];   // [H]
    const float* Wout  = (const float*)d_in[5];   // [1,H]
    const float* bout  = (const float*)d_in[6];   // [1]
    const float* beta1 = (const float*)d_in[7];
    const float* beta2 = (const float*)d_in[8];
    const float* betao = (const float*)d_in[9];
    float* out = (float*)d_out;                   // [B,T,1]

    cudaFuncSetAttribute(gemm_cur1,
                         cudaFuncAttributeMaxDynamicSharedMemorySize, GSMEM);

    dim3 ggrid(B * T / BM, H / BN);
    gemm_cur1<<<ggrid, 256, GSMEM>>>(x, W1, b1, W2);

    scan_kernel<<<B, 256>>>(b2, Wout, bout, beta1, beta2, betao, out);
}

// round 8
// speedup vs baseline: 1.0563x; 1.0214x over previous
#include <cuda_runtime.h>
#include <cuda_bf16.h>

// Problem dims (fixed by the dataset)
#define B  512
#define T  1024
#define IN 128
#define H  256

// ---------------- scratch (device globals: no allocation allowed) -------------
__device__ float    g_cur1[(size_t)B * T * H];   // [B][T][H]  512 MB
__device__ float    g_w2t[H * H];                // [j][h]  (W2 transposed)
__device__ unsigned g_spk[(size_t)B * T * 8];    // spk2 ballots, 16 MB

// packed fp32x2 helpers (sm_103a — only reachable via PTX)
#define FMA2(acc, a, b) \
    asm("fma.rn.f32x2 %0, %1, %2, %0;" : "+l"(acc) : "l"(a), "l"(b))
#define ADD2(d, a, b) \
    asm("add.rn.f32x2 %0, %1, %2;" : "=l"(d) : "l"(a), "l"(b))
#define PACK2(d, f) \
    asm("mov.b64 %0, {%1, %1};" : "=l"(d) : "r"(__float_as_uint(f)))

// ---------------- phase 1: cur1 = x @ W1^T + b1 -------------------------------
// 64x128 tile, two K-stages of 64, 4x8 micro-tile, FFMA2.
// W1 transposed inline during smem fill; blockIdx.x==0 also transposes W2.
#define BM  64
#define BN  128
#define BKK 64
#define BNP (BN + 4)
#define GSMEM ((BM * BKK + BKK * BNP) * 4)   // 50176 B -> opt-in dynamic smem

__global__ void __launch_bounds__(256) gemm_cur1(const float* __restrict__ x,
                                                 const float* __restrict__ W1,
                                                 const float* __restrict__ b1,
                                                 const float* __restrict__ W2) {
    extern __shared__ float smem_g[];
    float (*xs)[BKK] = (float(*)[BKK])smem_g;                    // 64x64
    float (*ws)[BNP] = (float(*)[BNP])(smem_g + BM * BKK);       // 64x132

    const int tid = threadIdx.x;

    if (blockIdx.x == 0) {                      // W2 transpose side-work
        int base = blockIdx.y * 256 + tid;
        #pragma unroll 4
        for (int i = 0; i < 128; i++) {
            int idx = base + i * 512;
            g_w2t[(idx & 255) * H + (idx >> 8)] = W2[idx];
        }
    }

    const int bm = blockIdx.x * BM;
    const int bn = blockIdx.y * BN;
    const int tx = tid & 15;
    const int ty = tid >> 4;

    unsigned long long acc[4][4];
    #pragma unroll
    for (int r = 0; r < 4; r++)
        #pragma unroll
        for (int p = 0; p < 4; p++) acc[r][p] = 0ull;

    for (int k0 = 0; k0 < IN; k0 += BKK) {
        #pragma unroll
        for (int l = 0; l < 4; l++) {
            int idx = tid + l * 256;
            int r = idx >> 4, c4 = idx & 15;
            *(float4*)&xs[r][c4 * 4] =
                *(const float4*)&x[(size_t)(bm + r) * IN + k0 + c4 * 4];
        }
        #pragma unroll
        for (int l = 0; l < 8; l++) {
            int k  = tid & 63;
            int hq = (tid >> 6) + l * 4;
            const float* w1p = &W1[(size_t)(bn + hq * 4) * IN + k0 + k];
            float4 v;
            v.x = w1p[0 * IN];
            v.y = w1p[1 * IN];
            v.z = w1p[2 * IN];
            v.w = w1p[3 * IN];
            *(float4*)&ws[k][hq * 4] = v;
        }
        __syncthreads();

        #pragma unroll 8
        for (int k = 0; k < BKK; k++) {
            ulonglong2 bq0 = *(ulonglong2*)&ws[k][tx * 8];
            ulonglong2 bq1 = *(ulonglong2*)&ws[k][tx * 8 + 4];
            #pragma unroll
            for (int r = 0; r < 4; r++) {
                unsigned long long ad;
                PACK2(ad, xs[ty * 4 + r][k]);
                FMA2(acc[r][0], ad, bq0.x);
                FMA2(acc[r][1], ad, bq0.y);
                FMA2(acc[r][2], ad, bq1.x);
                FMA2(acc[r][3], ad, bq1.y);
            }
        }
        __syncthreads();
    }

    ulonglong2 bias0 = *(const ulonglong2*)&b1[bn + tx * 8];
    ulonglong2 bias1 = *(const ulonglong2*)&b1[bn + tx * 8 + 4];
    #pragma unroll
    for (int r = 0; r < 4; r++) {
        ulonglong2 o0, o1;
        ADD2(o0.x, acc[r][0], bias0.x);
        ADD2(o0.y, acc[r][1], bias0.y);
        ADD2(o1.x, acc[r][2], bias1.x);
        ADD2(o1.y, acc[r][3], bias1.y);
        float* dst = &g_cur1[(size_t)(bm + ty * 4 + r) * H + bn + tx * 8];
        *(ulonglong2*)dst       = o0;
        *(ulonglong2*)(dst + 4) = o1;
    }
}

// ---------------- phase 2: sequential scan, one CTA per batch element ---------
// 256 threads. Warp w owns layer-1/2 neurons [32w, 32w+32) (thread tid = neuron
// tid) AND gather rows [32w, 32w+32). Lane l owns columns [4l,4l+4) and
// [128+4l,128+4l+4): both per-row LDG.128 are warp-contiguous 512B (4 wf, min).
// Gather mask = the warp's OWN ballot (no smem/barrier before gather).
// ONE __syncthreads per step (partials double-buffered).
// cur1 prefetched 4 steps deep (register ring) -> DRAM latency fully hidden.
__global__ void __launch_bounds__(256) scan_kernel(const float* __restrict__ b2,
                                                   const float* __restrict__ wout,
                                                   const float* __restrict__ boutp,
                                                   const float* __restrict__ pb1,
                                                   const float* __restrict__ pb2,
                                                   const float* __restrict__ pbo,
                                                   float* __restrict__ out) {
    const int b    = blockIdx.x;
    const int tid  = threadIdx.x;
    const int lane = tid & 31;
    const int wid  = tid >> 5;

    const float bt1 = fminf(fmaxf(pb1[0], 0.f), 1.f);
    const float bt2 = fminf(fmaxf(pb2[0], 0.f), 1.f);
    const float bto = fminf(fmaxf(pbo[0], 0.f), 1.f);
    const float boutv = boutp[0];
    const float b2v   = b2[tid];

    __shared__ float part[2][8][H];      // double-buffered partials (16KB)
    __shared__ float wout_sm[H];         // 1KB

    wout_sm[tid] = wout[tid];

    float mem1 = 0.f, mem2 = 0.f;
    float s1p = 0.f, s2p = 0.f;

    const float* c1p  = g_cur1 + (size_t)b * T * H + tid;
    unsigned*    spkp = g_spk + (size_t)b * T * 8;
    float*       outp = out + (size_t)b * T;
    // warp wid's row block; lane's two column quads (0..127 half and 128..255 half)
    const float* rbase = g_w2t + (size_t)(32 * wid) * H + lane * 4;

    // 4-deep prefetch ring for the cur1 DRAM stream
    float c0 = c1p[0 * H];
    float c1r = c1p[1 * H];
    float c2 = c1p[2 * H];
    float c3 = c1p[3 * H];
    __syncthreads();

    for (int t = 0; t < T; t++) {
        float c1 = c0;
        c0 = c1r; c1r = c2; c2 = c3;
        c3 = (t + 4 < T) ? c1p[(size_t)(t + 4) * H] : 0.f;   // issue early, MLP 4

        // layer 1 membrane update (reset uses previous-step spike)
        mem1 = bt1 * mem1 + c1 - s1p;
        bool s1 = mem1 > 1.0f;
        unsigned m = __ballot_sync(0xffffffffu, s1);   // == gather mask (own rows)
        s1p = s1 ? 1.f : 0.f;

        // gather: 2 rows in flight, 2 contiguous quads per row, packed adds
        ulonglong2 A0, A1, B0, B1;
        A0.x = A0.y = A1.x = A1.y = 0ull;
        B0.x = B0.y = B1.x = B1.y = 0ull;
        while (m) {
            int j0 = __ffs(m) - 1; m &= m - 1;
            const float* p0 = rbase + (size_t)j0 * H;
            if (m) {
                int j1 = __ffs(m) - 1; m &= m - 1;
                const float* p1 = rbase + (size_t)j1 * H;
                ulonglong2 w00 = *(const ulonglong2*)p0;            // cols 4l..
                ulonglong2 w01 = *(const ulonglong2*)(p0 + 128);    // cols 128+4l..
                ulonglong2 w10 = *(const ulonglong2*)p1;
                ulonglong2 w11 = *(const ulonglong2*)(p1 + 128);
                ADD2(A0.x, A0.x, w00.x); ADD2(A0.y, A0.y, w00.y);
                ADD2(A1.x, A1.x, w01.x); ADD2(A1.y, A1.y, w01.y);
                ADD2(B0.x, B0.x, w10.x); ADD2(B0.y, B0.y, w10.y);
                ADD2(B1.x, B1.x, w11.x); ADD2(B1.y, B1.y, w11.y);
            } else {
                ulonglong2 w00 = *(const ulonglong2*)p0;
                ulonglong2 w01 = *(const ulonglong2*)(p0 + 128);
                ADD2(A0.x, A0.x, w00.x); ADD2(A0.y, A0.y, w00.y);
                ADD2(A1.x, A1.x, w01.x); ADD2(A1.y, A1.y, w01.y);
            }
        }
        ADD2(A0.x, A0.x, B0.x); ADD2(A0.y, A0.y, B0.y);
        ADD2(A1.x, A1.x, B1.x); ADD2(A1.y, A1.y, B1.y);
        *(ulonglong2*)&part[t & 1][wid][lane * 4]       = A0;   // contiguous STS.128
        *(ulonglong2*)&part[t & 1][wid][128 + lane * 4] = A1;

        __syncthreads();                          // the ONE barrier per step

        // reduce 8 warp-partials for this thread's column
        const float* pp = &part[t & 1][0][tid];
        float r0 = pp[0 * H] + pp[1 * H];
        float r1 = pp[2 * H] + pp[3 * H];
        float r2 = pp[4 * H] + pp[5 * H];
        float r3 = pp[6 * H] + pp[7 * H];
        float cur2 = b2v + ((r0 + r1) + (r2 + r3));

        // layer 2 membrane update
        mem2 = bt2 * mem2 + cur2 - s2p;
        bool s2 = mem2 > 1.0f;
        s2p = s2 ? 1.f : 0.f;

        unsigned bal2 = __ballot_sync(0xffffffffu, s2);
        if (lane == 0) spkp[(size_t)t * 8 + wid] = bal2;
    }

    // ---------------- deferred output: out_t = bout + sum(spk2 .* wout) -------
    __syncthreads();
    float* out_s = &part[0][0][0];                // reuse smem as out_s[1024]
    #pragma unroll
    for (int i = 0; i < 4; i++) {
        int t = tid + i * 256;
        float o = boutv;
        #pragma unroll
        for (int w = 0; w < 8; w++) {
            unsigned m = spkp[(size_t)t * 8 + w];
            const float* wo = wout_sm + w * 32;
            while (m) {
                int j = __ffs(m) - 1; m &= m - 1;
                o += wo[j];
            }
        }
        out_s[t] = o;
    }
    __syncthreads();
    if (tid == 0) {                               // exact serial memo recurrence
        float memo = 0.f;
        for (int t = 0; t < T; t++) {
            memo = bto * memo + out_s[t];
            out_s[t] = memo;
        }
    }
    __syncthreads();
    #pragma unroll
    for (int i = 0; i < 4; i++) {
        int t = tid + i * 256;
        outp[t] = out_s[t];
    }
}

// ---------------- launcher ----------------------------------------------------
extern "C" void kernel_launch(void* const* d_in, const int* in_sizes, int n_in,
                              void* d_out, int out_size) {
    const float* x     = (const float*)d_in[0];   // [B,T,IN]
    const float* W1    = (const float*)d_in[1];   // [H,IN]
    const float* b1    = (const float*)d_in[2];   // [H]
    const float* W2    = (const float*)d_in[3];   // [H,H]
    const float* b2    = (const float*)d_in[4];   // [H]
    const float* Wout  = (const float*)d_in[5];   // [1,H]
    const float* bout  = (const float*)d_in[6];   // [1]
    const float* beta1 = (const float*)d_in[7];
    const float* beta2 = (const float*)d_in[8];
    const float* betao = (const float*)d_in[9];
    float* out = (float*)d_out;                   // [B,T,1]

    cudaFuncSetAttribute(gemm_cur1,
                         cudaFuncAttributeMaxDynamicSharedMemorySize, GSMEM);

    dim3 ggrid(B * T / BM, H / BN);
    gemm_cur1<<<ggrid, 256, GSMEM>>>(x, W1, b1, W2);

    scan_kernel<<<B, 256>>>(b2, Wout, bout, beta1, beta2, betao, out);
}

// round 9
// speedup vs baseline: 1.0651x; 1.0084x over previous
#include <cuda_runtime.h>
#include <cuda_bf16.h>

// Problem dims (fixed by the dataset)
#define B  512
#define T  1024
#define IN 128
#define H  256

// ---------------- scratch (device globals: no allocation allowed) -------------
__device__ float    g_cur1[(size_t)B * T * H];   // [B][T][H]  512 MB
__device__ float    g_w2t[H * H];                // [j][h]  (W2 transposed)
__device__ unsigned g_spk[(size_t)B * T * 8];    // spk2 ballots, 16 MB

// packed fp32x2 helpers (sm_103a — only reachable via PTX)
#define FMA2(acc, a, b) \
    asm("fma.rn.f32x2 %0, %1, %2, %0;" : "+l"(acc) : "l"(a), "l"(b))
#define ADD2(d, a, b) \
    asm("add.rn.f32x2 %0, %1, %2;" : "=l"(d) : "l"(a), "l"(b))
#define PACK2(d, f) \
    asm("mov.b64 %0, {%1, %1};" : "=l"(d) : "r"(__float_as_uint(f)))

// ---------------- phase 1: cur1 = x @ W1^T + b1 -------------------------------
// 64x128 tile, two K-stages of 64, 4x8 micro-tile, FFMA2.
// xs padded to stride 68: bank = (4r + k) % 32 -> 2-way max (was 16-way at
// stride 64, which made the whole GEMM crossbar-bound for 8 rounds).
// W1 transposed inline during smem fill; blockIdx.x==0 also transposes W2.
#define BM  64
#define BN  128
#define BKK 64
#define BKP 68           // xs row stride: 68 % 4 == 0 keeps float4 fills aligned
#define BNP (BN + 4)
#define GSMEM ((BM * BKP + BKK * BNP) * 4)   // 51200 B -> opt-in dynamic smem

__global__ void __launch_bounds__(256) gemm_cur1(const float* __restrict__ x,
                                                 const float* __restrict__ W1,
                                                 const float* __restrict__ b1,
                                                 const float* __restrict__ W2) {
    extern __shared__ float smem_g[];
    float (*xs)[BKP] = (float(*)[BKP])smem_g;                    // 64x68
    float (*ws)[BNP] = (float(*)[BNP])(smem_g + BM * BKP);       // 64x132

    const int tid = threadIdx.x;

    if (blockIdx.x == 0) {                      // W2 transpose side-work
        int base = blockIdx.y * 256 + tid;
        #pragma unroll 4
        for (int i = 0; i < 128; i++) {
            int idx = base + i * 512;
            g_w2t[(idx & 255) * H + (idx >> 8)] = W2[idx];
        }
    }

    const int bm = blockIdx.x * BM;
    const int bn = blockIdx.y * BN;
    const int tx = tid & 15;
    const int ty = tid >> 4;

    unsigned long long acc[4][4];
    #pragma unroll
    for (int r = 0; r < 4; r++)
        #pragma unroll
        for (int p = 0; p < 4; p++) acc[r][p] = 0ull;

    for (int k0 = 0; k0 < IN; k0 += BKK) {
        // xs: 64 rows x 64 floats (stride 68), 1024 float4, 4 per thread
        #pragma unroll
        for (int l = 0; l < 4; l++) {
            int idx = tid + l * 256;
            int r = idx >> 4, c4 = idx & 15;
            *(float4*)&xs[r][c4 * 4] =
                *(const float4*)&x[(size_t)(bm + r) * IN + k0 + c4 * 4];
        }
        // ws[k][h] = W1[bn+h][k0+k]: inline transpose
        #pragma unroll
        for (int l = 0; l < 8; l++) {
            int k  = tid & 63;
            int hq = (tid >> 6) + l * 4;
            const float* w1p = &W1[(size_t)(bn + hq * 4) * IN + k0 + k];
            float4 v;
            v.x = w1p[0 * IN];
            v.y = w1p[1 * IN];
            v.z = w1p[2 * IN];
            v.w = w1p[3 * IN];
            *(float4*)&ws[k][hq * 4] = v;
        }
        __syncthreads();

        #pragma unroll 8
        for (int k = 0; k < BKK; k++) {
            ulonglong2 bq0 = *(ulonglong2*)&ws[k][tx * 8];
            ulonglong2 bq1 = *(ulonglong2*)&ws[k][tx * 8 + 4];
            #pragma unroll
            for (int r = 0; r < 4; r++) {
                unsigned long long ad;
                PACK2(ad, xs[ty * 4 + r][k]);
                FMA2(acc[r][0], ad, bq0.x);
                FMA2(acc[r][1], ad, bq0.y);
                FMA2(acc[r][2], ad, bq1.x);
                FMA2(acc[r][3], ad, bq1.y);
            }
        }
        __syncthreads();
    }

    ulonglong2 bias0 = *(const ulonglong2*)&b1[bn + tx * 8];
    ulonglong2 bias1 = *(const ulonglong2*)&b1[bn + tx * 8 + 4];
    #pragma unroll
    for (int r = 0; r < 4; r++) {
        ulonglong2 o0, o1;
        ADD2(o0.x, acc[r][0], bias0.x);
        ADD2(o0.y, acc[r][1], bias0.y);
        ADD2(o1.x, acc[r][2], bias1.x);
        ADD2(o1.y, acc[r][3], bias1.y);
        float* dst = &g_cur1[(size_t)(bm + ty * 4 + r) * H + bn + tx * 8];
        *(ulonglong2*)dst       = o0;
        *(ulonglong2*)(dst + 4) = o1;
    }
}

// ---------------- phase 2: sequential scan, one CTA per batch element ---------
// (frozen at R8 state — isolate the GEMM change)
// 256 threads. Warp w owns layer-1/2 neurons [32w, 32w+32) AND gather rows
// [32w, 32w+32). Lane l owns columns [4l,4l+4) and [128+4l,128+4l+4): both
// per-row LDG.128 are warp-contiguous 512B. Gather mask = warp's OWN ballot.
// ONE __syncthreads per step (partials double-buffered). cur1 prefetch depth 4.
__global__ void __launch_bounds__(256) scan_kernel(const float* __restrict__ b2,
                                                   const float* __restrict__ wout,
                                                   const float* __restrict__ boutp,
                                                   const float* __restrict__ pb1,
                                                   const float* __restrict__ pb2,
                                                   const float* __restrict__ pbo,
                                                   float* __restrict__ out) {
    const int b    = blockIdx.x;
    const int tid  = threadIdx.x;
    const int lane = tid & 31;
    const int wid  = tid >> 5;

    const float bt1 = fminf(fmaxf(pb1[0], 0.f), 1.f);
    const float bt2 = fminf(fmaxf(pb2[0], 0.f), 1.f);
    const float bto = fminf(fmaxf(pbo[0], 0.f), 1.f);
    const float boutv = boutp[0];
    const float b2v   = b2[tid];

    __shared__ float part[2][8][H];      // double-buffered partials (16KB)
    __shared__ float wout_sm[H];         // 1KB

    wout_sm[tid] = wout[tid];

    float mem1 = 0.f, mem2 = 0.f;
    float s1p = 0.f, s2p = 0.f;

    const float* c1p  = g_cur1 + (size_t)b * T * H + tid;
    unsigned*    spkp = g_spk + (size_t)b * T * 8;
    float*       outp = out + (size_t)b * T;
    const float* rbase = g_w2t + (size_t)(32 * wid) * H + lane * 4;

    float c0 = c1p[0 * H];
    float c1r = c1p[1 * H];
    float c2 = c1p[2 * H];
    float c3 = c1p[3 * H];
    __syncthreads();

    for (int t = 0; t < T; t++) {
        float c1 = c0;
        c0 = c1r; c1r = c2; c2 = c3;
        c3 = (t + 4 < T) ? c1p[(size_t)(t + 4) * H] : 0.f;

        mem1 = bt1 * mem1 + c1 - s1p;
        bool s1 = mem1 > 1.0f;
        unsigned m = __ballot_sync(0xffffffffu, s1);
        s1p = s1 ? 1.f : 0.f;

        ulonglong2 A0, A1, B0, B1;
        A0.x = A0.y = A1.x = A1.y = 0ull;
        B0.x = B0.y = B1.x = B1.y = 0ull;
        while (m) {
            int j0 = __ffs(m) - 1; m &= m - 1;
            const float* p0 = rbase + (size_t)j0 * H;
            if (m) {
                int j1 = __ffs(m) - 1; m &= m - 1;
                const float* p1 = rbase + (size_t)j1 * H;
                ulonglong2 w00 = *(const ulonglong2*)p0;
                ulonglong2 w01 = *(const ulonglong2*)(p0 + 128);
                ulonglong2 w10 = *(const ulonglong2*)p1;
                ulonglong2 w11 = *(const ulonglong2*)(p1 + 128);
                ADD2(A0.x, A0.x, w00.x); ADD2(A0.y, A0.y, w00.y);
                ADD2(A1.x, A1.x, w01.x); ADD2(A1.y, A1.y, w01.y);
                ADD2(B0.x, B0.x, w10.x); ADD2(B0.y, B0.y, w10.y);
                ADD2(B1.x, B1.x, w11.x); ADD2(B1.y, B1.y, w11.y);
            } else {
                ulonglong2 w00 = *(const ulonglong2*)p0;
                ulonglong2 w01 = *(const ulonglong2*)(p0 + 128);
                ADD2(A0.x, A0.x, w00.x); ADD2(A0.y, A0.y, w00.y);
                ADD2(A1.x, A1.x, w01.x); ADD2(A1.y, A1.y, w01.y);
            }
        }
        ADD2(A0.x, A0.x, B0.x); ADD2(A0.y, A0.y, B0.y);
        ADD2(A1.x, A1.x, B1.x); ADD2(A1.y, A1.y, B1.y);
        *(ulonglong2*)&part[t & 1][wid][lane * 4]       = A0;
        *(ulonglong2*)&part[t & 1][wid][128 + lane * 4] = A1;

        __syncthreads();

        const float* pp = &part[t & 1][0][tid];
        float r0 = pp[0 * H] + pp[1 * H];
        float r1 = pp[2 * H] + pp[3 * H];
        float r2 = pp[4 * H] + pp[5 * H];
        float r3 = pp[6 * H] + pp[7 * H];
        float cur2 = b2v + ((r0 + r1) + (r2 + r3));

        mem2 = bt2 * mem2 + cur2 - s2p;
        bool s2 = mem2 > 1.0f;
        s2p = s2 ? 1.f : 0.f;

        unsigned bal2 = __ballot_sync(0xffffffffu, s2);
        if (lane == 0) spkp[(size_t)t * 8 + wid] = bal2;
    }

    // ---------------- deferred output: out_t = bout + sum(spk2 .* wout) -------
    __syncthreads();
    float* out_s = &part[0][0][0];
    #pragma unroll
    for (int i = 0; i < 4; i++) {
        int t = tid + i * 256;
        float o = boutv;
        #pragma unroll
        for (int w = 0; w < 8; w++) {
            unsigned m = spkp[(size_t)t * 8 + w];
            const float* wo = wout_sm + w * 32;
            while (m) {
                int j = __ffs(m) - 1; m &= m - 1;
                o += wo[j];
            }
        }
        out_s[t] = o;
    }
    __syncthreads();
    if (tid == 0) {
        float memo = 0.f;
        for (int t = 0; t < T; t++) {
            memo = bto * memo + out_s[t];
            out_s[t] = memo;
        }
    }
    __syncthreads();
    #pragma unroll
    for (int i = 0; i < 4; i++) {
        int t = tid + i * 256;
        outp[t] = out_s[t];
    }
}

// ---------------- launcher ----------------------------------------------------
extern "C" void kernel_launch(void* const* d_in, const int* in_sizes, int n_in,
                              void* d_out, int out_size) {
    const float* x     = (const float*)d_in[0];   // [B,T,IN]
    const float* W1    = (const float*)d_in[1];   // [H,IN]
    const float* b1    = (const float*)d_in[2];   // [H]
    const float* W2    = (const float*)d_in[3];   // [H,H]
    const float* b2    = (const float*)d_in[4];   // [H]
    const float* Wout  = (const float*)d_in[5];   // [1,H]
    const float* bout  = (const float*)d_in[6];   // [1]
    const float* beta1 = (const float*)d_in[7];
    const float* beta2 = (const float*)d_in[8];
    const float* betao = (const float*)d_in[9];
    float* out = (float*)d_out;                   // [B,T,1]

    cudaFuncSetAttribute(gemm_cur1,
                         cudaFuncAttributeMaxDynamicSharedMemorySize, GSMEM);

    dim3 ggrid(B * T / BM, H / BN);
    gemm_cur1<<<ggrid, 256, GSMEM>>>(x, W1, b1, W2);

    scan_kernel<<<B, 256>>>(b2, Wout, bout, beta1, beta2, betao, out);
}

// round 10
// speedup vs baseline: 1.0962x; 1.0291x over previous
#include <cuda_runtime.h>
#include <cuda_bf16.h>

// Problem dims (fixed by the dataset)
#define B  512
#define T  1024
#define IN 128
#define H  256

// ---------------- scratch (device globals: no allocation allowed) -------------
__device__ float    g_cur1[(size_t)B * T * H];   // [B][T][H]  512 MB
__device__ float    g_w2t[H * H];                // [j][h]  (W2 transposed)
__device__ unsigned g_spk[(size_t)B * T * 8];    // spk2 ballots, 16 MB

// packed fp32x2 helpers (sm_103a — only reachable via PTX)
#define FMA2(acc, a, b) \
    asm("fma.rn.f32x2 %0, %1, %2, %0;" : "+l"(acc) : "l"(a), "l"(b))
#define ADD2(d, a, b) \
    asm("add.rn.f32x2 %0, %1, %2;" : "=l"(d) : "l"(a), "l"(b))
#define PACK2(d, f) \
    asm("mov.b64 %0, {%1, %1};" : "=l"(d) : "r"(__float_as_uint(f)))

// probe: trailing no-op launch to shift ncu's skip-count onto gemm_cur1
__global__ void probe_kernel() {}

// ---------------- phase 1: cur1 = x @ W1^T + b1 -------------------------------
// 64x128 tile, two K-stages of 64, 4x8 micro-tile, FFMA2.
// xs stored K-MAJOR (xs_t[k][bt], pad 68): the 4 a-operands per k-step are one
// LDS.128 (contiguous bt) instead of 4 scalar LDS. b-operand unchanged.
// W1 transposed inline during smem fill; blockIdx.x==0 also transposes W2.
#define BM  64
#define BN  128
#define BKK 64
#define BMP 68           // xs_t row stride (floats); %4==0 keeps float4 aligned
#define BNP (BN + 4)
#define GSMEM ((BKK * BMP + BKK * BNP) * 4)   // 51200 B -> opt-in dynamic smem

__global__ void __launch_bounds__(256) gemm_cur1(const float* __restrict__ x,
                                                 const float* __restrict__ W1,
                                                 const float* __restrict__ b1,
                                                 const float* __restrict__ W2) {
    extern __shared__ float smem_g[];
    float (*xs_t)[BMP] = (float(*)[BMP])smem_g;                  // [k][bt] 64x68
    float (*ws)[BNP]   = (float(*)[BNP])(smem_g + BKK * BMP);    // [k][h]  64x132

    const int tid = threadIdx.x;

    if (blockIdx.x == 0) {                      // W2 transpose side-work
        int base = blockIdx.y * 256 + tid;
        #pragma unroll 4
        for (int i = 0; i < 128; i++) {
            int idx = base + i * 512;
            g_w2t[(idx & 255) * H + (idx >> 8)] = W2[idx];
        }
    }

    const int bm = blockIdx.x * BM;
    const int bn = blockIdx.y * BN;
    const int tx = tid & 15;
    const int ty = tid >> 4;

    unsigned long long acc[4][4];
    #pragma unroll
    for (int r = 0; r < 4; r++)
        #pragma unroll
        for (int p = 0; p < 4; p++) acc[r][p] = 0ull;

    for (int k0 = 0; k0 < IN; k0 += BKK) {
        // xs_t[k][bt] = x[bm+bt][k0+k]: inline transpose.
        // thread = (k, bt-quad): 4 coalesced scalar loads down 4 x rows + STS.128
        #pragma unroll
        for (int l = 0; l < 4; l++) {
            int k   = tid & 63;
            int bq4 = (tid >> 6) + l * 4;       // 0..15
            const float* xp = &x[(size_t)(bm + bq4 * 4) * IN + k0 + k];
            float4 v;
            v.x = xp[0 * IN];
            v.y = xp[1 * IN];
            v.z = xp[2 * IN];
            v.w = xp[3 * IN];
            *(float4*)&xs_t[k][bq4 * 4] = v;
        }
        // ws[k][h] = W1[bn+h][k0+k]: inline transpose
        #pragma unroll
        for (int l = 0; l < 8; l++) {
            int k  = tid & 63;
            int hq = (tid >> 6) + l * 4;
            const float* w1p = &W1[(size_t)(bn + hq * 4) * IN + k0 + k];
            float4 v;
            v.x = w1p[0 * IN];
            v.y = w1p[1 * IN];
            v.z = w1p[2 * IN];
            v.w = w1p[3 * IN];
            *(float4*)&ws[k][hq * 4] = v;
        }
        __syncthreads();

        #pragma unroll 8
        for (int k = 0; k < BKK; k++) {
            float4 av = *(float4*)&xs_t[k][ty * 4];            // a0..a3: ONE LDS.128
            ulonglong2 bq0 = *(ulonglong2*)&ws[k][tx * 8];
            ulonglong2 bq1 = *(ulonglong2*)&ws[k][tx * 8 + 4];
            unsigned long long a0, a1, a2, a3;
            PACK2(a0, av.x); PACK2(a1, av.y);
            PACK2(a2, av.z); PACK2(a3, av.w);
            FMA2(acc[0][0], a0, bq0.x); FMA2(acc[0][1], a0, bq0.y);
            FMA2(acc[0][2], a0, bq1.x); FMA2(acc[0][3], a0, bq1.y);
            FMA2(acc[1][0], a1, bq0.x); FMA2(acc[1][1], a1, bq0.y);
            FMA2(acc[1][2], a1, bq1.x); FMA2(acc[1][3], a1, bq1.y);
            FMA2(acc[2][0], a2, bq0.x); FMA2(acc[2][1], a2, bq0.y);
            FMA2(acc[2][2], a2, bq1.x); FMA2(acc[2][3], a2, bq1.y);
            FMA2(acc[3][0], a3, bq0.x); FMA2(acc[3][1], a3, bq0.y);
            FMA2(acc[3][2], a3, bq1.x); FMA2(acc[3][3], a3, bq1.y);
        }
        __syncthreads();
    }

    ulonglong2 bias0 = *(const ulonglong2*)&b1[bn + tx * 8];
    ulonglong2 bias1 = *(const ulonglong2*)&b1[bn + tx * 8 + 4];
    #pragma unroll
    for (int r = 0; r < 4; r++) {
        ulonglong2 o0, o1;
        ADD2(o0.x, acc[r][0], bias0.x);
        ADD2(o0.y, acc[r][1], bias0.y);
        ADD2(o1.x, acc[r][2], bias1.x);
        ADD2(o1.y, acc[r][3], bias1.y);
        float* dst = &g_cur1[(size_t)(bm + ty * 4 + r) * H + bn + tx * 8];
        *(ulonglong2*)dst       = o0;
        *(ulonglong2*)(dst + 4) = o1;
    }
}

// ---------------- phase 2: sequential scan, one CTA per batch element ---------
// (frozen at R8/R9 state)
__global__ void __launch_bounds__(256) scan_kernel(const float* __restrict__ b2,
                                                   const float* __restrict__ wout,
                                                   const float* __restrict__ boutp,
                                                   const float* __restrict__ pb1,
                                                   const float* __restrict__ pb2,
                                                   const float* __restrict__ pbo,
                                                   float* __restrict__ out) {
    const int b    = blockIdx.x;
    const int tid  = threadIdx.x;
    const int lane = tid & 31;
    const int wid  = tid >> 5;

    const float bt1 = fminf(fmaxf(pb1[0], 0.f), 1.f);
    const float bt2 = fminf(fmaxf(pb2[0], 0.f), 1.f);
    const float bto = fminf(fmaxf(pbo[0], 0.f), 1.f);
    const float boutv = boutp[0];
    const float b2v   = b2[tid];

    __shared__ float part[2][8][H];      // double-buffered partials (16KB)
    __shared__ float wout_sm[H];         // 1KB

    wout_sm[tid] = wout[tid];

    float mem1 = 0.f, mem2 = 0.f;
    float s1p = 0.f, s2p = 0.f;

    const float* c1p  = g_cur1 + (size_t)b * T * H + tid;
    unsigned*    spkp = g_spk + (size_t)b * T * 8;
    float*       outp = out + (size_t)b * T;
    const float* rbase = g_w2t + (size_t)(32 * wid) * H + lane * 4;

    float c0 = c1p[0 * H];
    float c1r = c1p[1 * H];
    float c2 = c1p[2 * H];
    float c3 = c1p[3 * H];
    __syncthreads();

    for (int t = 0; t < T; t++) {
        float c1 = c0;
        c0 = c1r; c1r = c2; c2 = c3;
        c3 = (t + 4 < T) ? c1p[(size_t)(t + 4) * H] : 0.f;

        mem1 = bt1 * mem1 + c1 - s1p;
        bool s1 = mem1 > 1.0f;
        unsigned m = __ballot_sync(0xffffffffu, s1);
        s1p = s1 ? 1.f : 0.f;

        ulonglong2 A0, A1, B0, B1;
        A0.x = A0.y = A1.x = A1.y = 0ull;
        B0.x = B0.y = B1.x = B1.y = 0ull;
        while (m) {
            int j0 = __ffs(m) - 1; m &= m - 1;
            const float* p0 = rbase + (size_t)j0 * H;
            if (m) {
                int j1 = __ffs(m) - 1; m &= m - 1;
                const float* p1 = rbase + (size_t)j1 * H;
                ulonglong2 w00 = *(const ulonglong2*)p0;
                ulonglong2 w01 = *(const ulonglong2*)(p0 + 128);
                ulonglong2 w10 = *(const ulonglong2*)p1;
                ulonglong2 w11 = *(const ulonglong2*)(p1 + 128);
                ADD2(A0.x, A0.x, w00.x); ADD2(A0.y, A0.y, w00.y);
                ADD2(A1.x, A1.x, w01.x); ADD2(A1.y, A1.y, w01.y);
                ADD2(B0.x, B0.x, w10.x); ADD2(B0.y, B0.y, w10.y);
                ADD2(B1.x, B1.x, w11.x); ADD2(B1.y, B1.y, w11.y);
            } else {
                ulonglong2 w00 = *(const ulonglong2*)p0;
                ulonglong2 w01 = *(const ulonglong2*)(p0 + 128);
                ADD2(A0.x, A0.x, w00.x); ADD2(A0.y, A0.y, w00.y);
                ADD2(A1.x, A1.x, w01.x); ADD2(A1.y, A1.y, w01.y);
            }
        }
        ADD2(A0.x, A0.x, B0.x); ADD2(A0.y, A0.y, B0.y);
        ADD2(A1.x, A1.x, B1.x); ADD2(A1.y, A1.y, B1.y);
        *(ulonglong2*)&part[t & 1][wid][lane * 4]       = A0;
        *(ulonglong2*)&part[t & 1][wid][128 + lane * 4] = A1;

        __syncthreads();

        const float* pp = &part[t & 1][0][tid];
        float r0 = pp[0 * H] + pp[1 * H];
        float r1 = pp[2 * H] + pp[3 * H];
        float r2 = pp[4 * H] + pp[5 * H];
        float r3 = pp[6 * H] + pp[7 * H];
        float cur2 = b2v + ((r0 + r1) + (r2 + r3));

        mem2 = bt2 * mem2 + cur2 - s2p;
        bool s2 = mem2 > 1.0f;
        s2p = s2 ? 1.f : 0.f;

        unsigned bal2 = __ballot_sync(0xffffffffu, s2);
        if (lane == 0) spkp[(size_t)t * 8 + wid] = bal2;
    }

    // ---------------- deferred output: out_t = bout + sum(spk2 .* wout) -------
    __syncthreads();
    float* out_s = &part[0][0][0];
    #pragma unroll
    for (int i = 0; i < 4; i++) {
        int t = tid + i * 256;
        float o = boutv;
        #pragma unroll
        for (int w = 0; w < 8; w++) {
            unsigned m = spkp[(size_t)t * 8 + w];
            const float* wo = wout_sm + w * 32;
            while (m) {
                int j = __ffs(m) - 1; m &= m - 1;
                o += wo[j];
            }
        }
        out_s[t] = o;
    }
    __syncthreads();
    if (tid == 0) {
        float memo = 0.f;
        for (int t = 0; t < T; t++) {
            memo = bto * memo + out_s[t];
            out_s[t] = memo;
        }
    }
    __syncthreads();
    #pragma unroll
    for (int i = 0; i < 4; i++) {
        int t = tid + i * 256;
        outp[t] = out_s[t];
    }
}

// ---------------- launcher ----------------------------------------------------
extern "C" void kernel_launch(void* const* d_in, const int* in_sizes, int n_in,
                              void* d_out, int out_size) {
    const float* x     = (const float*)d_in[0];   // [B,T,IN]
    const float* W1    = (const float*)d_in[1];   // [H,IN]
    const float* b1    = (const float*)d_in[2];   // [H]
    const float* W2    = (const float*)d_in[3];   // [H,H]
    const float* b2    = (const float*)d_in[4];   // [H]
    const float* Wout  = (const float*)d_in[5];   // [1,H]
    const float* bout  = (const float*)d_in[6];   // [1]
    const float* beta1 = (const float*)d_in[7];
    const float* beta2 = (const float*)d_in[8];
    const float* betao = (const float*)d_in[9];
    float* out = (float*)d_out;                   // [B,T,1]

    cudaFuncSetAttribute(gemm_cur1,
                         cudaFuncAttributeMaxDynamicSharedMemorySize, GSMEM);

    dim3 ggrid(B * T / BM, H / BN);
    gemm_cur1<<<ggrid, 256, GSMEM>>>(x, W1, b1, W2);

    scan_kernel<<<B, 256>>>(b2, Wout, bout, beta1, beta2, betao, out);

    probe_kernel<<<1, 32>>>();   // parity-shift so ncu skip-5 lands on gemm_cur1
}

// round 11
// speedup vs baseline: 1.4231x; 1.2982x over previous
#include <cuda_runtime.h>
#include <cuda_bf16.h>

// Problem dims (fixed by the dataset)
#define B  512
#define T  1024
#define IN 128
#define H  256

// ---------------- scratch (device globals: no allocation allowed) -------------
__device__ float    g_cur1[(size_t)B * T * H];   // [B][T][H]  512 MB
__device__ float    g_w2t[H * H];                // [j][h]  (W2 transposed)
__device__ unsigned g_spk[(size_t)B * T * 8];    // spk2 ballots, 16 MB

// packed fp32x2 helpers (sm_103a — only reachable via PTX)
#define FMA2(acc, a, b) \
    asm("fma.rn.f32x2 %0, %1, %2, %0;" : "+l"(acc) : "l"(a), "l"(b))
#define ADD2(d, a, b) \
    asm("add.rn.f32x2 %0, %1, %2;" : "=l"(d) : "l"(a), "l"(b))
#define PACK2(d, f) \
    asm("mov.b64 %0, {%1, %1};" : "=l"(d) : "r"(__float_as_uint(f)))

// probe: trailing no-op launch to shift ncu's skip-count onto gemm_cur1
__global__ void probe_kernel() {}

// ---------------- phase 1: cur1 = x @ W1^T + b1 -------------------------------
// 128x128 tile, K-stages of 32, 8x8 micro-tile (rows/cols split 0/64), FFMA2.
// Inner loop: 4 LDS.128 per k-step, ALL conflict-free:
//   a: xs_t[k][ty*4], xs_t[k][64+ty*4]  (lanes 0-15 broadcast)
//   b: ws [k][tx*4], ws [k][64+tx*4]   (lanes contiguous 256B)
// (previous layout had b at 32B lane stride -> 4-way bank conflict -> L1 96.5%)
#define BM  128
#define BN  128
#define BKK 32
#define STR 132          // smem row stride (floats), %4==0 for float4 fills

__global__ void __launch_bounds__(256) gemm_cur1(const float* __restrict__ x,
                                                 const float* __restrict__ W1,
                                                 const float* __restrict__ b1,
                                                 const float* __restrict__ W2) {
    __shared__ float xs_t[BKK][STR];   // [k][bt]
    __shared__ float ws[BKK][STR];     // [k][h]

    const int tid = threadIdx.x;

    if (blockIdx.x == 0) {                      // W2 transpose side-work (2 blocks)
        int base = blockIdx.y * 256 + tid;
        #pragma unroll 4
        for (int i = 0; i < 128; i++) {
            int idx = base + i * 512;
            g_w2t[(idx & 255) * H + (idx >> 8)] = W2[idx];
        }
    }

    const int bm = blockIdx.x * BM;
    const int bn = blockIdx.y * BN;
    const int tx = tid & 15;        // col quads tx*4 and 64+tx*4
    const int ty = tid >> 4;        // row quads ty*4 and 64+ty*4

    unsigned long long acc[8][4];
    #pragma unroll
    for (int r = 0; r < 8; r++)
        #pragma unroll
        for (int p = 0; p < 4; p++) acc[r][p] = 0ull;

    for (int k0 = 0; k0 < IN; k0 += BKK) {
        // fill xs_t[k][bt] = x[bm+bt][k0+k] (transpose; LDG coalesced over k)
        #pragma unroll
        for (int l = 0; l < 4; l++) {
            int k  = tid & 31;
            int qq = (tid >> 5) + l * 8;        // 0..31, bt quad
            const float* xp = &x[(size_t)(bm + qq * 4) * IN + k0 + k];
            float4 v;
            v.x = xp[0 * IN];
            v.y = xp[1 * IN];
            v.z = xp[2 * IN];
            v.w = xp[3 * IN];
            *(float4*)&xs_t[k][qq * 4] = v;
        }
        // fill ws[k][h] = W1[bn+h][k0+k]
        #pragma unroll
        for (int l = 0; l < 4; l++) {
            int k  = tid & 31;
            int hq = (tid >> 5) + l * 8;        // 0..31, h quad
            const float* w1p = &W1[(size_t)(bn + hq * 4) * IN + k0 + k];
            float4 v;
            v.x = w1p[0 * IN];
            v.y = w1p[1 * IN];
            v.z = w1p[2 * IN];
            v.w = w1p[3 * IN];
            *(float4*)&ws[k][hq * 4] = v;
        }
        __syncthreads();

        #pragma unroll 8
        for (int k = 0; k < BKK; k++) {
            float4 a0v = *(float4*)&xs_t[k][ty * 4];
            float4 a1v = *(float4*)&xs_t[k][64 + ty * 4];
            ulonglong2 bv0 = *(ulonglong2*)&ws[k][tx * 4];        // cols tx*4..+3
            ulonglong2 bv1 = *(ulonglong2*)&ws[k][64 + tx * 4];   // cols 64+tx*4..
            unsigned long long A[8];
            PACK2(A[0], a0v.x); PACK2(A[1], a0v.y);
            PACK2(A[2], a0v.z); PACK2(A[3], a0v.w);
            PACK2(A[4], a1v.x); PACK2(A[5], a1v.y);
            PACK2(A[6], a1v.z); PACK2(A[7], a1v.w);
            #pragma unroll
            for (int r = 0; r < 8; r++) {
                FMA2(acc[r][0], A[r], bv0.x);
                FMA2(acc[r][1], A[r], bv0.y);
                FMA2(acc[r][2], A[r], bv1.x);
                FMA2(acc[r][3], A[r], bv1.y);
            }
        }
        __syncthreads();
    }

    // bias + store: rows {bm+ty*4+i, bm+64+ty*4+i}, cols {bn+tx*4.., bn+64+tx*4..}
    ulonglong2 bias0 = *(const ulonglong2*)&b1[bn + tx * 4];
    ulonglong2 bias1 = *(const ulonglong2*)&b1[bn + 64 + tx * 4];
    #pragma unroll
    for (int r = 0; r < 8; r++) {
        int row = bm + ((r < 4) ? (ty * 4 + r) : (64 + ty * 4 + r - 4));
        ulonglong2 o0, o1;
        ADD2(o0.x, acc[r][0], bias0.x);
        ADD2(o0.y, acc[r][1], bias0.y);
        ADD2(o1.x, acc[r][2], bias1.x);
        ADD2(o1.y, acc[r][3], bias1.y);
        float* dst = &g_cur1[(size_t)row * H + bn];
        *(ulonglong2*)(dst + tx * 4)      = o0;
        *(ulonglong2*)(dst + 64 + tx * 4) = o1;
    }
}

// ---------------- phase 2: sequential scan, one CTA per batch element ---------
// (frozen at R8/R9 state)
__global__ void __launch_bounds__(256) scan_kernel(const float* __restrict__ b2,
                                                   const float* __restrict__ wout,
                                                   const float* __restrict__ boutp,
                                                   const float* __restrict__ pb1,
                                                   const float* __restrict__ pb2,
                                                   const float* __restrict__ pbo,
                                                   float* __restrict__ out) {
    const int b    = blockIdx.x;
    const int tid  = threadIdx.x;
    const int lane = tid & 31;
    const int wid  = tid >> 5;

    const float bt1 = fminf(fmaxf(pb1[0], 0.f), 1.f);
    const float bt2 = fminf(fmaxf(pb2[0], 0.f), 1.f);
    const float bto = fminf(fmaxf(pbo[0], 0.f), 1.f);
    const float boutv = boutp[0];
    const float b2v   = b2[tid];

    __shared__ float part[2][8][H];      // double-buffered partials (16KB)
    __shared__ float wout_sm[H];         // 1KB

    wout_sm[tid] = wout[tid];

    float mem1 = 0.f, mem2 = 0.f;
    float s1p = 0.f, s2p = 0.f;

    const float* c1p  = g_cur1 + (size_t)b * T * H + tid;
    unsigned*    spkp = g_spk + (size_t)b * T * 8;
    float*       outp = out + (size_t)b * T;
    const float* rbase = g_w2t + (size_t)(32 * wid) * H + lane * 4;

    float c0 = c1p[0 * H];
    float c1r = c1p[1 * H];
    float c2 = c1p[2 * H];
    float c3 = c1p[3 * H];
    __syncthreads();

    for (int t = 0; t < T; t++) {
        float c1 = c0;
        c0 = c1r; c1r = c2; c2 = c3;
        c3 = (t + 4 < T) ? c1p[(size_t)(t + 4) * H] : 0.f;

        mem1 = bt1 * mem1 + c1 - s1p;
        bool s1 = mem1 > 1.0f;
        unsigned m = __ballot_sync(0xffffffffu, s1);
        s1p = s1 ? 1.f : 0.f;

        ulonglong2 A0, A1, B0, B1;
        A0.x = A0.y = A1.x = A1.y = 0ull;
        B0.x = B0.y = B1.x = B1.y = 0ull;
        while (m) {
            int j0 = __ffs(m) - 1; m &= m - 1;
            const float* p0 = rbase + (size_t)j0 * H;
            if (m) {
                int j1 = __ffs(m) - 1; m &= m - 1;
                const float* p1 = rbase + (size_t)j1 * H;
                ulonglong2 w00 = *(const ulonglong2*)p0;
                ulonglong2 w01 = *(const ulonglong2*)(p0 + 128);
                ulonglong2 w10 = *(const ulonglong2*)p1;
                ulonglong2 w11 = *(const ulonglong2*)(p1 + 128);
                ADD2(A0.x, A0.x, w00.x); ADD2(A0.y, A0.y, w00.y);
                ADD2(A1.x, A1.x, w01.x); ADD2(A1.y, A1.y, w01.y);
                ADD2(B0.x, B0.x, w10.x); ADD2(B0.y, B0.y, w10.y);
                ADD2(B1.x, B1.x, w11.x); ADD2(B1.y, B1.y, w11.y);
            } else {
                ulonglong2 w00 = *(const ulonglong2*)p0;
                ulonglong2 w01 = *(const ulonglong2*)(p0 + 128);
                ADD2(A0.x, A0.x, w00.x); ADD2(A0.y, A0.y, w00.y);
                ADD2(A1.x, A1.x, w01.x); ADD2(A1.y, A1.y, w01.y);
            }
        }
        ADD2(A0.x, A0.x, B0.x); ADD2(A0.y, A0.y, B0.y);
        ADD2(A1.x, A1.x, B1.x); ADD2(A1.y, A1.y, B1.y);
        *(ulonglong2*)&part[t & 1][wid][lane * 4]       = A0;
        *(ulonglong2*)&part[t & 1][wid][128 + lane * 4] = A1;

        __syncthreads();

        const float* pp = &part[t & 1][0][tid];
        float r0 = pp[0 * H] + pp[1 * H];
        float r1 = pp[2 * H] + pp[3 * H];
        float r2 = pp[4 * H] + pp[5 * H];
        float r3 = pp[6 * H] + pp[7 * H];
        float cur2 = b2v + ((r0 + r1) + (r2 + r3));

        mem2 = bt2 * mem2 + cur2 - s2p;
        bool s2 = mem2 > 1.0f;
        s2p = s2 ? 1.f : 0.f;

        unsigned bal2 = __ballot_sync(0xffffffffu, s2);
        if (lane == 0) spkp[(size_t)t * 8 + wid] = bal2;
    }

    // ---------------- deferred output: out_t = bout + sum(spk2 .* wout) -------
    __syncthreads();
    float* out_s = &part[0][0][0];
    #pragma unroll
    for (int i = 0; i < 4; i++) {
        int t = tid + i * 256;
        float o = boutv;
        #pragma unroll
        for (int w = 0; w < 8; w++) {
            unsigned m = spkp[(size_t)t * 8 + w];
            const float* wo = wout_sm + w * 32;
            while (m) {
                int j = __ffs(m) - 1; m &= m - 1;
                o += wo[j];
            }
        }
        out_s[t] = o;
    }
    __syncthreads();
    if (tid == 0) {
        float memo = 0.f;
        for (int t = 0; t < T; t++) {
            memo = bto * memo + out_s[t];
            out_s[t] = memo;
        }
    }
    __syncthreads();
    #pragma unroll
    for (int i = 0; i < 4; i++) {
        int t = tid + i * 256;
        outp[t] = out_s[t];
    }
}

// ---------------- launcher ----------------------------------------------------
extern "C" void kernel_launch(void* const* d_in, const int* in_sizes, int n_in,
                              void* d_out, int out_size) {
    const float* x     = (const float*)d_in[0];   // [B,T,IN]
    const float* W1    = (const float*)d_in[1];   // [H,IN]
    const float* b1    = (const float*)d_in[2];   // [H]
    const float* W2    = (const float*)d_in[3];   // [H,H]
    const float* b2    = (const float*)d_in[4];   // [H]
    const float* Wout  = (const float*)d_in[5];   // [1,H]
    const float* bout  = (const float*)d_in[6];   // [1]
    const float* beta1 = (const float*)d_in[7];
    const float* beta2 = (const float*)d_in[8];
    const float* betao = (const float*)d_in[9];
    float* out = (float*)d_out;                   // [B,T,1]

    dim3 ggrid(B * T / BM, H / BN);
    gemm_cur1<<<ggrid, 256>>>(x, W1, b1, W2);

    scan_kernel<<<B, 256>>>(b2, Wout, bout, beta1, beta2, betao, out);

    probe_kernel<<<1, 32>>>();   // parity-shift so ncu skip-5 lands on gemm_cur1
}